// round 14
// baseline (speedup 1.0000x reference)
#include <cuda_runtime.h>
#include <cuda_fp16.h>
#include <cstdint>

// GQA flash attention, FA2-style, mma.sync.m16n8k16.
// Round 14: 2 CTAs/SM (STAGES=2, <=128 regs via launch_bounds; Q A-frags
// reloaded from smem per iter). fp16 K/V prepass + cp.async pipeline,
// static-shift softmax, l via ones-column MMA.
// q: [2,32,2048,128] f32   k,v: [2,8,2048,128] f32   out: [2,32,2048,128] f32

#define BM      128
#define BN      64
#define DH      128
#define DPAD    136     // smem row stride in halves (272B)
#define THREADS 256
#define SQ      2048
#define SKV     2048
#define NQH     32
#define NKVH    8
#define NITER   (SKV / BN)
#define STAGES  2

#define KV_ELEMS (2 * NKVH * SKV * DH)

#define SM_Q      0
#define Q_HALVES  (BM * DPAD)                 // 17408 halves
#define TILE_H    (BN * DPAD)                 // 8704 halves
#define SM_KV     Q_HALVES
#define SMEM_BYTES ((Q_HALVES + STAGES * 2 * TILE_H) * 2)   // 104448 B -> 2 CTAs/SM

__device__ __align__(16) __half g_k16[KV_ELEMS];
__device__ __align__(16) __half g_v16[KV_ELEMS];

__device__ __forceinline__ uint32_t smem_u32(const void* p) {
    return (uint32_t)__cvta_generic_to_shared(p);
}
__device__ __forceinline__ void ldsm_x4(uint32_t& r0, uint32_t& r1, uint32_t& r2, uint32_t& r3, uint32_t a) {
    asm volatile("ldmatrix.sync.aligned.m8n8.x4.shared.b16 {%0,%1,%2,%3}, [%4];"
                 : "=r"(r0), "=r"(r1), "=r"(r2), "=r"(r3) : "r"(a));
}
__device__ __forceinline__ void ldsm_x4_t(uint32_t& r0, uint32_t& r1, uint32_t& r2, uint32_t& r3, uint32_t a) {
    asm volatile("ldmatrix.sync.aligned.m8n8.x4.trans.shared.b16 {%0,%1,%2,%3}, [%4];"
                 : "=r"(r0), "=r"(r1), "=r"(r2), "=r"(r3) : "r"(a));
}
__device__ __forceinline__ void ldsm_x2_t(uint32_t& r0, uint32_t& r1, uint32_t a) {
    asm volatile("ldmatrix.sync.aligned.m8n8.x2.trans.shared.b16 {%0,%1}, [%2];"
                 : "=r"(r0), "=r"(r1) : "r"(a));
}
__device__ __forceinline__ void mma16816(float* c, const uint32_t* a, uint32_t b0, uint32_t b1) {
    asm volatile("mma.sync.aligned.m16n8k16.row.col.f32.f16.f16.f32 "
                 "{%0,%1,%2,%3}, {%4,%5,%6,%7}, {%8,%9}, {%0,%1,%2,%3};"
                 : "+f"(c[0]), "+f"(c[1]), "+f"(c[2]), "+f"(c[3])
                 : "r"(a[0]), "r"(a[1]), "r"(a[2]), "r"(a[3]), "r"(b0), "r"(b1));
}
__device__ __forceinline__ uint2 cvt4(float4 f) {
    __half2 lo = __floats2half2_rn(f.x, f.y);
    __half2 hi = __floats2half2_rn(f.z, f.w);
    uint2 r;
    r.x = *(uint32_t*)&lo;
    r.y = *(uint32_t*)&hi;
    return r;
}
__device__ __forceinline__ uint32_t ex2h2(float a, float b) {
    __half2 h = __floats2half2_rn(a, b);
    uint32_t r;
    asm("ex2.approx.f16x2 %0, %1;" : "=r"(r) : "r"(*(uint32_t*)&h));
    return r;
}
#define CP_COMMIT() asm volatile("cp.async.commit_group;" ::: "memory")
#define CP_WAIT(n)  asm volatile("cp.async.wait_group %0;" :: "n"(n) : "memory")

__device__ __forceinline__ void issue_kv(uint32_t ksm, uint32_t vsm,
                                         const __half* kg, const __half* vg, int tid) {
    #pragma unroll
    for (int j = 0; j < 4; j++) {
        int c = tid + j * THREADS;
        uint32_t soff = (uint32_t)((c >> 4) * (DPAD * 2) + (c & 15) * 16);
        asm volatile("cp.async.cg.shared.global [%0], [%1], 16;"
                     :: "r"(ksm + soff), "l"(kg + c * 8) : "memory");
    }
    #pragma unroll
    for (int j = 0; j < 4; j++) {
        int c = tid + j * THREADS;
        uint32_t soff = (uint32_t)((c >> 4) * (DPAD * 2) + (c & 15) * 16);
        asm volatile("cp.async.cg.shared.global [%0], [%1], 16;"
                     :: "r"(vsm + soff), "l"(vg + c * 8) : "memory");
    }
}

// ---------------- prepass: fp32 -> fp16 K/V scratch ----------------
__global__ void __launch_bounds__(256, 4)
cvt_kv_kernel(const float4* __restrict__ k, const float4* __restrict__ v) {
    int i = blockIdx.x * 256 + threadIdx.x;
    ((uint2*)g_k16)[i] = cvt4(k[i]);
    ((uint2*)g_v16)[i] = cvt4(v[i]);
}

extern __shared__ __align__(16) __half dsm[];

__global__ void __launch_bounds__(THREADS, 2)
fa_gqa_kernel(const float* __restrict__ q, float* __restrict__ out) {
    const int qt = blockIdx.x;
    const int bh = blockIdx.y;
    const int b  = bh >> 5;
    const int h  = bh & 31;
    const int kvh = b * NKVH + (h >> 2);

    const float*  qb = q + ((size_t)bh * SQ + (size_t)qt * BM) * DH;
    const __half* kb = g_k16 + (size_t)kvh * SKV * DH;
    const __half* vb = g_v16 + (size_t)kvh * SKV * DH;
    float*        ob = out + ((size_t)bh * SQ + (size_t)qt * BM) * DH;

    const int tid  = threadIdx.x;
    const int w    = tid >> 5;
    const int lane = tid & 31;
    const uint32_t sb = smem_u32(dsm);

    // issue stage 0 & 1 fills
    {
        uint32_t k0 = sb + SM_KV * 2;
        issue_kv(k0, k0 + TILE_H * 2, kb, vb, tid);
        CP_COMMIT();
        uint32_t k1 = sb + (SM_KV + 2 * TILE_H) * 2;
        issue_kv(k1, k1 + TILE_H * 2, kb + BN * DH, vb + BN * DH, tid);
        CP_COMMIT();
    }

    // ones-column init for both V buffers
    if (tid < 64 * STAGES) {
        int s   = tid >> 6;
        int row = tid & 63;
        __half* Vp = dsm + SM_KV + (2 * s + 1) * TILE_H;
        *(uint4*)&Vp[row * DPAD + 128] = make_uint4(0x3C00u, 0u, 0u, 0u);
    }

    // stage Q (fp32 -> fp16); stays resident in smem (A-frags reloaded per iter)
    {
        const float4* qv = (const float4*)qb;
        #pragma unroll
        for (int i = 0; i < 16; i++) {
            int vi   = tid + i * THREADS;
            int row  = vi >> 5;
            int colv = vi & 31;
            *(uint2*)&dsm[SM_Q + row * DPAD + colv * 4] = cvt4(qv[vi]);
        }
    }

    float o_acc[16][4];
    #pragma unroll
    for (int j = 0; j < 16; j++) { o_acc[j][0]=0.f; o_acc[j][1]=0.f; o_acc[j][2]=0.f; o_acc[j][3]=0.f; }
    float o_l[4] = {0.f, 0.f, 0.f, 0.f};

    const float SCL = 0.08838834764831845f * 1.4426950408889634f;  // 1/sqrt(128)*log2(e)

    const int lr = lane & 15;
    const int lc = (lane >> 4) * 8;
    const int qr = w * 16 + lr;          // Q fragment row for ldmatrix

    __syncthreads();   // Q staged before first in-loop aq load

    int stage = 0;
    for (int it = 0; it < NITER; ++it) {
        CP_WAIT(1);
        __syncthreads();   // stage `it` visible to all warps

        const __half* Ks = dsm + SM_KV + 2 * stage * TILE_H;
        const __half* Vs = Ks + TILE_H;

        // reload Q A-fragments (frees 32 regs from permanent residency)
        uint32_t aq[8][4];
        #pragma unroll
        for (int kb8 = 0; kb8 < 8; kb8++) {
            uint32_t addr = smem_u32(&dsm[SM_Q + qr * DPAD + kb8 * 16 + lc]);
            ldsm_x4(aq[kb8][0], aq[kb8][1], aq[kb8][2], aq[kb8][3], addr);
        }

        // ---- fused blocks: S-MMA(16 cols) -> softmax -> PV-MMA ----
        #pragma unroll
        for (int jj = 0; jj < 4; jj++) {
            float s0[4] = {0.f, 0.f, 0.f, 0.f};
            float s1[4] = {0.f, 0.f, 0.f, 0.f};
            #pragma unroll
            for (int kb8 = 0; kb8 < 8; kb8++) {
                uint32_t b0, b1, b2, b3;
                uint32_t addr = smem_u32(&Ks[(jj * 16 + lr) * DPAD + kb8 * 16 + lc]);
                ldsm_x4(b0, b1, b2, b3, addr);
                mma16816(s0, aq[kb8], b0, b2);
                mma16816(s1, aq[kb8], b1, b3);
            }

            uint32_t ap[4];
            ap[0] = ex2h2(fmaf(s0[0], SCL, -4.0f), fmaf(s0[1], SCL, -4.0f));
            ap[1] = ex2h2(fmaf(s0[2], SCL, -4.0f), fmaf(s0[3], SCL, -4.0f));
            ap[2] = ex2h2(fmaf(s1[0], SCL, -4.0f), fmaf(s1[1], SCL, -4.0f));
            ap[3] = ex2h2(fmaf(s1[2], SCL, -4.0f), fmaf(s1[3], SCL, -4.0f));

            #pragma unroll
            for (int jd = 0; jd < 8; jd++) {
                uint32_t r0, r1, r2, r3;
                uint32_t addr = smem_u32(&Vs[(jj * 16 + lr) * DPAD + jd * 16 + lc]);
                ldsm_x4_t(r0, r1, r2, r3, addr);
                mma16816(o_acc[2 * jd],     ap, r0, r1);
                mma16816(o_acc[2 * jd + 1], ap, r2, r3);
            }
            uint32_t l0, l1;
            uint32_t laddr = smem_u32(&Vs[(jj * 16 + lr) * DPAD + 128]);
            ldsm_x2_t(l0, l1, laddr);
            mma16816(o_l, ap, l0, l1);
        }

        __syncthreads();   // all warps done reading stage `it` buffers

        // refill current buffer with tile it+2
        if (it + 2 < NITER) {
            uint32_t kd = sb + (SM_KV + 2 * stage * TILE_H) * 2;
            issue_kv(kd, kd + TILE_H * 2,
                     kb + (size_t)(it + 2) * BN * DH, vb + (size_t)(it + 2) * BN * DH, tid);
        }
        CP_COMMIT();

        stage ^= 1;
    }

    // ---------- epilogue ----------
    const float lv0 = __shfl_sync(0xffffffffu, o_l[0], lane & 28);
    const float lv1 = __shfl_sync(0xffffffffu, o_l[2], lane & 28);
    const float inv0 = 1.0f / lv0;
    const float inv1 = 1.0f / lv1;
    const int r0row = w * 16 + (lane >> 2);
    const int r1row = r0row + 8;
    const int cbase = (lane & 3) * 2;
    #pragma unroll
    for (int jd = 0; jd < 16; jd++) {
        int col = jd * 8 + cbase;
        *(float2*)&ob[(size_t)r0row * DH + col] = make_float2(o_acc[jd][0] * inv0, o_acc[jd][1] * inv0);
        *(float2*)&ob[(size_t)r1row * DH + col] = make_float2(o_acc[jd][2] * inv1, o_acc[jd][3] * inv1);
    }
}

extern "C" void kernel_launch(void* const* d_in, const int* in_sizes, int n_in,
                              void* d_out, int out_size) {
    const long long QELEMS = (long long)2 * NQH * SQ * DH;
    int qi = 0;
    for (int i = 0; i < n_in && i < 3; i++)
        if ((long long)in_sizes[i] == QELEMS) { qi = i; break; }
    int rest[2], r = 0;
    for (int i = 0; i < 3; i++) if (i != qi) rest[r++] = i;

    const float* q = (const float*)d_in[qi];
    const float* k = (const float*)d_in[rest[0]];
    const float* v = (const float*)d_in[rest[1]];
    float* o = (float*)d_out;

    static int smem_set = 0;
    if (!smem_set) {
        cudaFuncSetAttribute(fa_gqa_kernel, cudaFuncAttributeMaxDynamicSharedMemorySize, SMEM_BYTES);
        smem_set = 1;
    }

    cvt_kv_kernel<<<KV_ELEMS / 4 / 256, 256>>>((const float4*)k, (const float4*)v);
    dim3 grid(SQ / BM, 2 * NQH);
    fa_gqa_kernel<<<grid, THREADS, SMEM_BYTES>>>(q, o);
}

// round 16
// speedup vs baseline: 1.5623x; 1.5623x over previous
#include <cuda_runtime.h>
#include <cuda_fp16.h>
#include <cstdint>

// GQA flash attention, FA2-style, mma.sync.m16n8k16.
// Round 15: BM=256 (32 q-rows/warp, 2 m-tiles) -> K/V smem reads serve 2x MMA
// work; tensor-bound regime. fp16 K/V prepass + cp.async 3-stage pipeline,
// block-fused softmax (f16x2 ex2), static shift, l via ones-column MMA.
// q: [2,32,2048,128] f32   k,v: [2,8,2048,128] f32   out: [2,32,2048,128] f32

#define BM      256
#define BN      64
#define DH      128
#define DPAD    136     // smem row stride in halves (272B)
#define THREADS 256
#define SQ      2048
#define SKV     2048
#define NQH     32
#define NKVH    8
#define NITER   (SKV / BN)
#define STAGES  3

#define KV_ELEMS (2 * NKVH * SKV * DH)

#define SM_Q      0
#define Q_HALVES  (BM * DPAD)                 // 34816 halves (69632 B)
#define TILE_H    (BN * DPAD)                 // 8704 halves
#define SM_KV     Q_HALVES
#define SMEM_BYTES ((Q_HALVES + STAGES * 2 * TILE_H) * 2)   // 174080 B

__device__ __align__(16) __half g_k16[KV_ELEMS];
__device__ __align__(16) __half g_v16[KV_ELEMS];

__device__ __forceinline__ uint32_t smem_u32(const void* p) {
    return (uint32_t)__cvta_generic_to_shared(p);
}
__device__ __forceinline__ void ldsm_x4(uint32_t& r0, uint32_t& r1, uint32_t& r2, uint32_t& r3, uint32_t a) {
    asm volatile("ldmatrix.sync.aligned.m8n8.x4.shared.b16 {%0,%1,%2,%3}, [%4];"
                 : "=r"(r0), "=r"(r1), "=r"(r2), "=r"(r3) : "r"(a));
}
__device__ __forceinline__ void ldsm_x4_t(uint32_t& r0, uint32_t& r1, uint32_t& r2, uint32_t& r3, uint32_t a) {
    asm volatile("ldmatrix.sync.aligned.m8n8.x4.trans.shared.b16 {%0,%1,%2,%3}, [%4];"
                 : "=r"(r0), "=r"(r1), "=r"(r2), "=r"(r3) : "r"(a));
}
__device__ __forceinline__ void ldsm_x2_t(uint32_t& r0, uint32_t& r1, uint32_t a) {
    asm volatile("ldmatrix.sync.aligned.m8n8.x2.trans.shared.b16 {%0,%1}, [%2];"
                 : "=r"(r0), "=r"(r1) : "r"(a));
}
__device__ __forceinline__ void mma16816(float* c, const uint32_t* a, uint32_t b0, uint32_t b1) {
    asm volatile("mma.sync.aligned.m16n8k16.row.col.f32.f16.f16.f32 "
                 "{%0,%1,%2,%3}, {%4,%5,%6,%7}, {%8,%9}, {%0,%1,%2,%3};"
                 : "+f"(c[0]), "+f"(c[1]), "+f"(c[2]), "+f"(c[3])
                 : "r"(a[0]), "r"(a[1]), "r"(a[2]), "r"(a[3]), "r"(b0), "r"(b1));
}
__device__ __forceinline__ uint2 cvt4(float4 f) {
    __half2 lo = __floats2half2_rn(f.x, f.y);
    __half2 hi = __floats2half2_rn(f.z, f.w);
    uint2 r;
    r.x = *(uint32_t*)&lo;
    r.y = *(uint32_t*)&hi;
    return r;
}
__device__ __forceinline__ uint32_t ex2h2(float a, float b) {
    __half2 h = __floats2half2_rn(a, b);
    uint32_t r;
    asm("ex2.approx.f16x2 %0, %1;" : "=r"(r) : "r"(*(uint32_t*)&h));
    return r;
}
#define CP_COMMIT() asm volatile("cp.async.commit_group;" ::: "memory")
#define CP_WAIT(n)  asm volatile("cp.async.wait_group %0;" :: "n"(n) : "memory")

__device__ __forceinline__ void issue_kv(uint32_t ksm, uint32_t vsm,
                                         const __half* kg, const __half* vg, int tid) {
    #pragma unroll
    for (int j = 0; j < 4; j++) {
        int c = tid + j * THREADS;
        uint32_t soff = (uint32_t)((c >> 4) * (DPAD * 2) + (c & 15) * 16);
        asm volatile("cp.async.cg.shared.global [%0], [%1], 16;"
                     :: "r"(ksm + soff), "l"(kg + c * 8) : "memory");
    }
    #pragma unroll
    for (int j = 0; j < 4; j++) {
        int c = tid + j * THREADS;
        uint32_t soff = (uint32_t)((c >> 4) * (DPAD * 2) + (c & 15) * 16);
        asm volatile("cp.async.cg.shared.global [%0], [%1], 16;"
                     :: "r"(vsm + soff), "l"(vg + c * 8) : "memory");
    }
}

// ---------------- prepass: fp32 -> fp16 K/V scratch ----------------
__global__ void __launch_bounds__(256, 4)
cvt_kv_kernel(const float4* __restrict__ k, const float4* __restrict__ v) {
    int i = blockIdx.x * 256 + threadIdx.x;
    ((uint2*)g_k16)[i] = cvt4(k[i]);
    ((uint2*)g_v16)[i] = cvt4(v[i]);
}

extern __shared__ __align__(16) __half dsm[];

__global__ void __launch_bounds__(THREADS, 1)
fa_gqa_kernel(const float* __restrict__ q, float* __restrict__ out) {
    const int qt = blockIdx.x;            // 0..7 (256-row q tiles)
    const int bh = blockIdx.y;
    const int b  = bh >> 5;
    const int h  = bh & 31;
    const int kvh = b * NKVH + (h >> 2);

    const float*  qb = q + ((size_t)bh * SQ + (size_t)qt * BM) * DH;
    const __half* kb = g_k16 + (size_t)kvh * SKV * DH;
    const __half* vb = g_v16 + (size_t)kvh * SKV * DH;
    float*        ob = out + ((size_t)bh * SQ + (size_t)qt * BM) * DH;

    const int tid  = threadIdx.x;
    const int w    = tid >> 5;
    const int lane = tid & 31;
    const uint32_t sb = smem_u32(dsm);

    // issue stage 0 & 1 fills
    {
        uint32_t k0 = sb + SM_KV * 2;
        issue_kv(k0, k0 + TILE_H * 2, kb, vb, tid);
        CP_COMMIT();
        uint32_t k1 = sb + (SM_KV + 2 * TILE_H) * 2;
        issue_kv(k1, k1 + TILE_H * 2, kb + BN * DH, vb + BN * DH, tid);
        CP_COMMIT();
    }

    // ones-column init for all V buffers
    if (tid < 64 * STAGES) {
        int s   = tid >> 6;
        int row = tid & 63;
        __half* Vp = dsm + SM_KV + (2 * s + 1) * TILE_H;
        *(uint4*)&Vp[row * DPAD + 128] = make_uint4(0x3C00u, 0u, 0u, 0u);
    }

    // stage Q (256 x 128, fp32 -> fp16)
    {
        const float4* qv = (const float4*)qb;
        #pragma unroll
        for (int i = 0; i < 32; i++) {
            int vi   = tid + i * THREADS;
            int row  = vi >> 5;
            int colv = vi & 31;
            *(uint2*)&dsm[SM_Q + row * DPAD + colv * 4] = cvt4(qv[vi]);
        }
    }
    __syncthreads();

    const int lr = lane & 15;
    const int lc = (lane >> 4) * 8;

    // Q A-fragments for both m-tiles (held in registers)
    uint32_t aq[2][8][4];
    #pragma unroll
    for (int mt = 0; mt < 2; mt++) {
        const int qr = w * 32 + mt * 16 + lr;
        #pragma unroll
        for (int kb8 = 0; kb8 < 8; kb8++) {
            uint32_t addr = smem_u32(&dsm[SM_Q + qr * DPAD + kb8 * 16 + lc]);
            ldsm_x4(aq[mt][kb8][0], aq[mt][kb8][1], aq[mt][kb8][2], aq[mt][kb8][3], addr);
        }
    }

    float o_acc[2][16][4];
    #pragma unroll
    for (int mt = 0; mt < 2; mt++)
        #pragma unroll
        for (int j = 0; j < 16; j++) {
            o_acc[mt][j][0]=0.f; o_acc[mt][j][1]=0.f; o_acc[mt][j][2]=0.f; o_acc[mt][j][3]=0.f;
        }
    float o_l[2][4] = {{0.f,0.f,0.f,0.f},{0.f,0.f,0.f,0.f}};

    const float SCL = 0.08838834764831845f * 1.4426950408889634f;  // 1/sqrt(128)*log2(e)

    int stage = 0;
    for (int it = 0; it < NITER; ++it) {
        CP_WAIT(1);
        __syncthreads();

        // issue stage it+2 into the ring
        {
            int ns = stage + 2;
            if (ns >= STAGES) ns -= STAGES;
            if (it + 2 < NITER) {
                uint32_t kd = sb + (SM_KV + 2 * ns * TILE_H) * 2;
                issue_kv(kd, kd + TILE_H * 2,
                         kb + (size_t)(it + 2) * BN * DH, vb + (size_t)(it + 2) * BN * DH, tid);
            }
            CP_COMMIT();
        }

        const __half* Ks = dsm + SM_KV + 2 * stage * TILE_H;
        const __half* Vs = Ks + TILE_H;

        // ---- fused blocks: S-MMA(16 kv cols, 2 m-tiles) -> softmax -> PV ----
        #pragma unroll
        for (int jj = 0; jj < 4; jj++) {
            float s0[2][4], s1[2][4];
            #pragma unroll
            for (int mt = 0; mt < 2; mt++) {
                s0[mt][0]=0.f; s0[mt][1]=0.f; s0[mt][2]=0.f; s0[mt][3]=0.f;
                s1[mt][0]=0.f; s1[mt][1]=0.f; s1[mt][2]=0.f; s1[mt][3]=0.f;
            }
            #pragma unroll
            for (int kb8 = 0; kb8 < 8; kb8++) {
                uint32_t b0, b1, b2, b3;
                uint32_t addr = smem_u32(&Ks[(jj * 16 + lr) * DPAD + kb8 * 16 + lc]);
                ldsm_x4(b0, b1, b2, b3, addr);
                #pragma unroll
                for (int mt = 0; mt < 2; mt++) {
                    mma16816(s0[mt], aq[mt][kb8], b0, b2);
                    mma16816(s1[mt], aq[mt][kb8], b1, b3);
                }
            }

            uint32_t ap[2][4];
            #pragma unroll
            for (int mt = 0; mt < 2; mt++) {
                ap[mt][0] = ex2h2(fmaf(s0[mt][0], SCL, -4.0f), fmaf(s0[mt][1], SCL, -4.0f));
                ap[mt][1] = ex2h2(fmaf(s0[mt][2], SCL, -4.0f), fmaf(s0[mt][3], SCL, -4.0f));
                ap[mt][2] = ex2h2(fmaf(s1[mt][0], SCL, -4.0f), fmaf(s1[mt][1], SCL, -4.0f));
                ap[mt][3] = ex2h2(fmaf(s1[mt][2], SCL, -4.0f), fmaf(s1[mt][3], SCL, -4.0f));
            }

            #pragma unroll
            for (int jd = 0; jd < 8; jd++) {
                uint32_t r0, r1, r2, r3;
                uint32_t addr = smem_u32(&Vs[(jj * 16 + lr) * DPAD + jd * 16 + lc]);
                ldsm_x4_t(r0, r1, r2, r3, addr);
                #pragma unroll
                for (int mt = 0; mt < 2; mt++) {
                    mma16816(o_acc[mt][2 * jd],     ap[mt], r0, r1);
                    mma16816(o_acc[mt][2 * jd + 1], ap[mt], r2, r3);
                }
            }
            uint32_t l0, l1;
            uint32_t laddr = smem_u32(&Vs[(jj * 16 + lr) * DPAD + 128]);
            ldsm_x2_t(l0, l1, laddr);
            #pragma unroll
            for (int mt = 0; mt < 2; mt++)
                mma16816(o_l[mt], ap[mt], l0, l1);
        }

        if (++stage == STAGES) stage = 0;
    }

    // ---------- epilogue (2 m-tiles) ----------
    #pragma unroll
    for (int mt = 0; mt < 2; mt++) {
        const float lv0 = __shfl_sync(0xffffffffu, o_l[mt][0], lane & 28);
        const float lv1 = __shfl_sync(0xffffffffu, o_l[mt][2], lane & 28);
        const float inv0 = 1.0f / lv0;
        const float inv1 = 1.0f / lv1;
        const int r0row = w * 32 + mt * 16 + (lane >> 2);
        const int r1row = r0row + 8;
        const int cbase = (lane & 3) * 2;
        #pragma unroll
        for (int jd = 0; jd < 16; jd++) {
            int col = jd * 8 + cbase;
            *(float2*)&ob[(size_t)r0row * DH + col] =
                make_float2(o_acc[mt][jd][0] * inv0, o_acc[mt][jd][1] * inv0);
            *(float2*)&ob[(size_t)r1row * DH + col] =
                make_float2(o_acc[mt][jd][2] * inv1, o_acc[mt][jd][3] * inv1);
        }
    }
}

extern "C" void kernel_launch(void* const* d_in, const int* in_sizes, int n_in,
                              void* d_out, int out_size) {
    const long long QELEMS = (long long)2 * NQH * SQ * DH;
    int qi = 0;
    for (int i = 0; i < n_in && i < 3; i++)
        if ((long long)in_sizes[i] == QELEMS) { qi = i; break; }
    int rest[2], r = 0;
    for (int i = 0; i < 3; i++) if (i != qi) rest[r++] = i;

    const float* q = (const float*)d_in[qi];
    const float* k = (const float*)d_in[rest[0]];
    const float* v = (const float*)d_in[rest[1]];
    float* o = (float*)d_out;

    static int smem_set = 0;
    if (!smem_set) {
        cudaFuncSetAttribute(fa_gqa_kernel, cudaFuncAttributeMaxDynamicSharedMemorySize, SMEM_BYTES);
        smem_set = 1;
    }

    cvt_kv_kernel<<<KV_ELEMS / 4 / 256, 256>>>((const float4*)k, (const float4*)v);
    dim3 grid(SQ / BM, 2 * NQH);   // 8 x 64 = 512 CTAs
    fa_gqa_kernel<<<grid, THREADS, SMEM_BYTES>>>(q, o);
}